// round 13
// baseline (speedup 1.0000x reference)
#include <cuda_runtime.h>

// CRF loss, T=512, B=1024, K=48. R13: each half-sequence job is computed by a
// PAIR of warps (a "slot"): warp half h owns output states h*24+lane, holding
// only its 24-pair weight table (48 regs). The 48-state P vector ping-pongs in
// slot-shared smem; per-step sync = named bar.sync(slot+1, 64). 592 blocks x
// 128 threads (4/SM, 16 warps): slot 0 (warps 0-1) = forward jobs, slot 1
// (warps 2-3) = backward jobs, LPT queues. Linear-space recursion, exact
// power-of-2 renorm folded into ex2 (every 2 steps), 24 fma.rn.f32x2/warp.

#define TT 512
#define BB 1024
#define KK 48
#define NBLKW 592
#define START_TAG 46
#define STOP_TAG  47
#define LN2F  0.6931471805599453f
#define LOG2E 1.4426950408889634f
#define PFD 6

__device__ float g_partial[BB];
__device__ float g_fwdv[BB * KK];
__device__ float g_bwdv[BB * KK];
__device__ float g_gold[BB];
__device__ int   g_cf[BB];
__device__ int   g_cb[BB];
__device__ int   g_flag[BB];
__device__ int   g_order[BB];      // rank -> batch (longest first)
__device__ int   g_next_f, g_next_b, g_done;

__device__ __forceinline__ unsigned long long pack2(float lo, float hi) {
    unsigned long long r;
    asm("mov.b64 %0, {%1, %2};" : "=l"(r) : "f"(lo), "f"(hi));
    return r;
}
__device__ __forceinline__ void unpack2(unsigned long long v, float& lo, float& hi) {
    asm("mov.b64 {%0, %1}, %2;" : "=f"(lo), "=f"(hi) : "l"(v));
}
__device__ __forceinline__ unsigned long long fma2(unsigned long long a,
                                                   unsigned long long b,
                                                   unsigned long long c) {
    unsigned long long d;
    asm("fma.rn.f32x2 %0, %1, %2, %3;" : "=l"(d) : "l"(a), "l"(b), "l"(c));
    return d;
}
__device__ __forceinline__ unsigned long long add2(unsigned long long a,
                                                   unsigned long long b) {
    unsigned long long d;
    asm("add.rn.f32x2 %0, %1, %2;" : "=l"(d) : "l"(a), "l"(b));
    return d;
}
__device__ __forceinline__ float ex2f(float x) {
    float r;
    asm("ex2.approx.f32 %0, %1;" : "=f"(r) : "f"(x));
    return r;
}

// ---------- pre-pass: longest-first rank + counter/flag reset --------------
__global__ void perm_kernel(const int* __restrict__ lengths) {
    __shared__ int s_len[BB];
    const int tid = threadIdx.x;
    const int b = blockIdx.x * 512 + tid;
    s_len[tid] = lengths[tid];
    s_len[tid + 512] = lengths[tid + 512];
    __syncthreads();

    const int lb = s_len[b];
    int k = 0;
    #pragma unroll 8
    for (int j = 0; j < BB; j++) {
        int lj = s_len[j];
        k += (lj > lb) || (lj == lb && j < b);
    }
    g_order[k] = b;
    g_flag[b] = 0;
    if (b == 0) { g_next_f = 0; g_next_b = 0; g_done = 0; }
}

#define SLOTBAR() asm volatile("bar.sync %0, 64;" :: "r"(slot + 1) : "memory")

// one recursion step for THIS lane's single output state
#define STEP(PIN, POUT, FC, RENORM)                                          \
    do {                                                                     \
        const ulonglong2* pv = (const ulonglong2*)(PIN);                     \
        ulonglong2 e0 = pv[0];                                               \
        unsigned long long c0 = fma2(e0.x, etw[0], 0ull);                    \
        unsigned long long c1 = fma2(e0.y, etw[1], 0ull);                    \
        unsigned long long c2 = 0ull, c3 = 0ull;                             \
        _Pragma("unroll")                                                    \
        for (int q = 1; q < 12; q++) {                                       \
            ulonglong2 e = pv[q];                                            \
            if (q & 1) {                                                     \
                c2 = fma2(e.x, etw[2*q],     c2);                            \
                c3 = fma2(e.y, etw[2*q + 1], c3);                            \
            } else {                                                         \
                c0 = fma2(e.x, etw[2*q],     c0);                            \
                c1 = fma2(e.y, etw[2*q + 1], c1);                            \
            }                                                                \
        }                                                                    \
        unsigned long long sum = add2(add2(c0, c2), add2(c1, c3));           \
        float fpe = 0.0f;                                                    \
        if (RENORM) {                                                        \
            unsigned int pexp = ((unsigned)e0.x) >> 23;                      \
            int pe = (pexp - 1u < 254u) ? (int)pexp - 127 : 0;               \
            Cint += pe;                                                      \
            fpe = (float)(-pe);                                              \
        }                                                                    \
        float mm = ex2f(fmaf((FC), LOG2E, fpe));                             \
        float lo, hi;                                                        \
        unpack2(sum, lo, hi);                                                \
        (POUT)[sidx] = (lo + hi) * mm;                                       \
    } while (0)

#define RUNLOOP(NSTEPS)                                                      \
    do {                                                                     \
        int t = 0;                                                           \
        _Pragma("unroll 1")                                                  \
        while (t + 1 < (NSTEPS)) {                                           \
            {                                                                \
                float fc = r1;                                               \
                r1 = r2; r2 = r3; r3 = r4; r4 = r5; r5 = r6;                 \
                r6 = (t < pre) ? __ldg(pf) : 0.0f;                           \
                pf += pstep;                                                 \
                STEP(spA, spB, fc, true);                                    \
            }                                                                \
            SLOTBAR();                                                       \
            {                                                                \
                float fc = r1;                                               \
                r1 = r2; r2 = r3; r3 = r4; r4 = r5; r5 = r6;                 \
                r6 = (t + 1 < pre) ? __ldg(pf) : 0.0f;                       \
                pf += pstep;                                                 \
                STEP(spB, spA, fc, false);                                   \
            }                                                                \
            SLOTBAR();                                                       \
            t += 2;                                                          \
        }                                                                    \
        if (t < (NSTEPS)) {                                                  \
            float fc = r1;                                                   \
            STEP(spA, spB, fc, true);                                        \
            SLOTBAR();                                                       \
        }                                                                    \
    } while (0)

// second finisher (one warp): combine halves; last batch -> final sum
#define COMBINE(BATCH)                                                       \
    do {                                                                     \
        __threadfence();                                                     \
        float v = 0.0f;                                                      \
        if (act) {                                                           \
            float2 pfv = *(const float2*)&g_fwdv[(BATCH) * KK + 2 * lane];   \
            float2 bbv = *(const float2*)&g_bwdv[(BATCH) * KK + 2 * lane];   \
            v = pfv.x * bbv.x + pfv.y * bbv.y;                               \
        }                                                                    \
        _Pragma("unroll")                                                    \
        for (int o = 16; o; o >>= 1) v += __shfl_xor_sync(~0u, v, o);        \
        float logz = (float)(g_cf[BATCH] + g_cb[BATCH]) * LN2F + __logf(v);  \
        int l2 = 0;                                                          \
        if (lane == 0) {                                                     \
            g_partial[BATCH] = logz - g_gold[BATCH];                         \
            __threadfence();                                                 \
            int p2 = atomicAdd(&g_done, 1);                                  \
            l2 = (p2 == BB - 1);                                             \
        }                                                                    \
        l2 = __shfl_sync(~0u, l2, 0);                                        \
        if (l2) {                                                            \
            __threadfence();                                                 \
            float a = 0.0f;                                                  \
            _Pragma("unroll")                                                \
            for (int i = 0; i < BB / 32; i++)                                \
                a += g_partial[lane + i * 32];                               \
            _Pragma("unroll")                                                \
            for (int o = 16; o; o >>= 1) a += __shfl_xor_sync(~0u, a, o);    \
            if (lane == 0) out[0] = a;                                       \
        }                                                                    \
    } while (0)

__global__ void __launch_bounds__(128, 4) crf_kernel(
    const float* __restrict__ feats,
    const float* __restrict__ trans,
    const int*   __restrict__ tags,
    const int*   __restrict__ lengths,
    float*       __restrict__ out)
{
    __shared__ float s_trans[KK * KK];
    __shared__ __align__(16) float s_pp[2][2][64];  // [slot][buf][state+pad]
    __shared__ int s_job[2];

    const int tid  = threadIdx.x;
    const int wid  = tid >> 5;
    const int lane = tid & 31;
    const int slot = wid >> 1;          // 0 = fwd slot, 1 = bwd slot
    const int half = wid & 1;           // which 24-state half this warp owns
    const bool is_fwd = (slot == 0);
    const bool act = (lane < 24);
    const int l24 = act ? lane : 23;
    const int st  = half * 24 + l24;    // owned output state (clamped)
    const int sidx = act ? (half * 24 + lane) : (48 + half * 8 + (lane - 24));

    for (int i = tid; i < KK * KK; i += 128) s_trans[i] = trans[i];
    __syncthreads();

    // per-lane weight pairs: fwd etw[q] = {e^T[st,2q], e^T[st,2q+1]},
    //                        bwd etw[q] = {e^T[2q,st], e^T[2q+1,st]}
    unsigned long long etw[24];
    #pragma unroll
    for (int i = 0; i < 24; i++) {
        if (is_fwd)
            etw[i] = pack2(__expf(s_trans[st * KK + 2*i]),
                           __expf(s_trans[st * KK + 2*i + 1]));
        else
            etw[i] = pack2(__expf(s_trans[(2*i) * KK + st]),
                           __expf(s_trans[(2*i + 1) * KK + st]));
    }
    const float stp = __expf(s_trans[STOP_TAG * KK + st]);
    const long long FS = (long long)BB * KK;
    const long long pstep = is_fwd ? FS : -FS;
    int* qn = is_fwd ? &g_next_f : &g_next_b;

    float* spA = s_pp[slot][0];
    float* spB = s_pp[slot][1];

    for (;;) {
        if (half == 0 && lane == 0) s_job[slot] = atomicAdd(qn, 1);
        SLOTBAR();
        const int j = s_job[slot];
        if (j >= BB) break;
        const int b   = __ldg(&g_order[j]);
        const int len = __ldg(lengths + b);
        const int m   = len >> 1;
        const int nst = is_fwd ? m : (len - m);
        const float* fbs = feats + (long long)b * KK + st;
        const float* fb0 = feats + (long long)b * KK;

        int Cint = 0;
        float r1 = 0.f, r2 = 0.f, r3 = 0.f, r4 = 0.f, r5 = 0.f, r6 = 0.f;
        const float* pf;
        int pre;
        if (is_fwd) {
            spA[sidx] = (sidx == START_TAG) ? 1.0f : 0.0f;
            spB[sidx] = 0.0f;
            r1 = __ldg(fbs);                       // t=0 (len >= 1)
            if (1 < nst) r2 = __ldg(fbs + 1 * FS);
            if (2 < nst) r3 = __ldg(fbs + 2 * FS);
            if (3 < nst) r4 = __ldg(fbs + 3 * FS);
            if (4 < nst) r5 = __ldg(fbs + 4 * FS);
            if (5 < nst) r6 = __ldg(fbs + 5 * FS);
            pf = fbs + (long long)PFD * FS;
            pre = nst - PFD;
        } else {
            float f0 = __ldg(fbs + (long long)(len - 1) * FS);
            spA[sidx] = stp * ex2f(f0 * LOG2E);    // W_{len-1}
            spB[sidx] = 0.0f;
            if (0 < nst - 1) r1 = __ldg(fbs + (long long)(len - 2) * FS);
            if (1 < nst - 1) r2 = __ldg(fbs + (long long)(len - 3) * FS);
            if (2 < nst - 1) r3 = __ldg(fbs + (long long)(len - 4) * FS);
            if (3 < nst - 1) r4 = __ldg(fbs + (long long)(len - 5) * FS);
            if (4 < nst - 1) r5 = __ldg(fbs + (long long)(len - 6) * FS);
            if (5 < nst - 1) r6 = __ldg(fbs + (long long)(len - 7) * FS);
            pf = fbs + (long long)(len - 2 - PFD) * FS;
            pre = nst - 1 - PFD;
        }
        SLOTBAR();

        RUNLOOP(nst);

        // write this warp's half of the meeting vector (self-owned states)
        {
            const float* spf = (nst & 1) ? spB : spA;
            float* gv = is_fwd ? g_fwdv : g_bwdv;
            if (act) gv[b * KK + st] = spf[sidx];
        }

        if (is_fwd && half == 0) {
            // gold score over the full sequence (32 lanes)
            const int* tg = tags + b * TT;
            float g = 0.0f;
            for (int q2 = lane; q2 < len; q2 += 32) {
                int nxt = __ldg(tg + q2);
                int prv = (q2 == 0) ? START_TAG : __ldg(tg + q2 - 1);
                g += s_trans[nxt * KK + prv] + __ldg(fb0 + (long long)q2 * FS + nxt);
            }
            #pragma unroll
            for (int o = 16; o; o >>= 1) g += __shfl_xor_sync(~0u, g, o);
            if (lane == 0) {
                g_gold[b] = g + s_trans[STOP_TAG * KK + __ldg(tg + len - 1)];
                g_cf[b] = Cint;
            }
        }
        if (!is_fwd && half == 0 && lane == 0) g_cb[b] = Cint;

        __threadfence();
        SLOTBAR();

        if (half == 0) {
            int prev = 0;
            if (lane == 0) prev = atomicAdd(&g_flag[b], 1);
            prev = __shfl_sync(~0u, prev, 0);
            if (prev == 1) COMBINE(b);
        }
    }
}

extern "C" void kernel_launch(void* const* d_in, const int* in_sizes, int n_in,
                              void* d_out, int out_size) {
    const float* feats   = (const float*)d_in[0];
    const float* trans   = (const float*)d_in[1];
    const int*   tags    = (const int*)d_in[2];
    const int*   lengths = (const int*)d_in[3];
    perm_kernel<<<2, 512>>>(lengths);
    crf_kernel<<<NBLKW, 128>>>(feats, trans, tags, lengths, (float*)d_out);
}

// round 14
// speedup vs baseline: 1.2254x; 1.2254x over previous
#include <cuda_runtime.h>

// CRF loss, T=512, B=1024, K=48. R14: fwd/bwd split (2048 half-jobs), ONE
// single-warp block per job, grid 2048 = one wave at 14 blocks/SM
// (launch_bounds(32,14), reg cap 146 — fits the 96-reg etp table without
// spills; smem = 512B/block since trans is read via __ldg for prologue/gold).
// LPT: block bid runs job rank bid>>1 (longest first), dir = bid&1.
// Step body = R11: linear-space recursion, smem ping-pong {P_2i,P_2i+1},
// 12 broadcast LDS.128 + 48 fma.rn.f32x2 / 8 accumulators per step, exact
// power-of-2 renorm every 2 steps folded into ex2.

#define TT 512
#define BB 1024
#define KK 48
#define NBLK 2048
#define START_TAG 46
#define STOP_TAG  47
#define LN2F  0.6931471805599453f
#define LOG2E 1.4426950408889634f
#define PFD 4

__device__ float g_partial[BB];
__device__ float g_fwdv[BB * KK];
__device__ float g_bwdv[BB * KK];
__device__ float g_gold[BB];
__device__ int   g_cf[BB];
__device__ int   g_cb[BB];
__device__ int   g_flag[BB];
__device__ int   g_order[BB];      // rank -> batch (longest first)
__device__ int   g_done;

__device__ __forceinline__ unsigned long long pack2(float lo, float hi) {
    unsigned long long r;
    asm("mov.b64 %0, {%1, %2};" : "=l"(r) : "f"(lo), "f"(hi));
    return r;
}
__device__ __forceinline__ void unpack2(unsigned long long v, float& lo, float& hi) {
    asm("mov.b64 {%0, %1}, %2;" : "=f"(lo), "=f"(hi) : "l"(v));
}
__device__ __forceinline__ unsigned long long fma2(unsigned long long a,
                                                   unsigned long long b,
                                                   unsigned long long c) {
    unsigned long long d;
    asm("fma.rn.f32x2 %0, %1, %2, %3;" : "=l"(d) : "l"(a), "l"(b), "l"(c));
    return d;
}
__device__ __forceinline__ unsigned long long add2(unsigned long long a,
                                                   unsigned long long b) {
    unsigned long long d;
    asm("add.rn.f32x2 %0, %1, %2;" : "=l"(d) : "l"(a), "l"(b));
    return d;
}
__device__ __forceinline__ float ex2f(float x) {
    float r;
    asm("ex2.approx.f32 %0, %1;" : "=f"(r) : "f"(x));
    return r;
}

// ---------- pre-pass: longest-first rank + flag/counter reset --------------
__global__ void perm_kernel(const int* __restrict__ lengths) {
    __shared__ int s_len[BB];
    const int tid = threadIdx.x;
    const int b = blockIdx.x * 512 + tid;
    s_len[tid] = lengths[tid];
    s_len[tid + 512] = lengths[tid + 512];
    __syncthreads();

    const int lb = s_len[b];
    int k = 0;
    #pragma unroll 8
    for (int j = 0; j < BB; j++) {
        int lj = s_len[j];
        k += (lj > lb) || (lj == lb && j < b);
    }
    g_order[k] = b;
    g_flag[b] = 0;
    if (b == 0) g_done = 0;
}

// ---------- one recursion step ---------------------------------------------
#define STEP(PIN, POUT, FC, RENORM)                                          \
    do {                                                                     \
        const ulonglong2* pv = (const ulonglong2*)(PIN);                     \
        ulonglong2 e0 = pv[0];                                               \
        unsigned long long c0 = fma2(e0.x, etp0[0], 0ull);                   \
        unsigned long long c2 = fma2(e0.y, etp0[1], 0ull);                   \
        unsigned long long c4 = fma2(e0.x, etp1[0], 0ull);                   \
        unsigned long long c6 = fma2(e0.y, etp1[1], 0ull);                   \
        unsigned long long c1 = 0ull, c3 = 0ull, c5 = 0ull, c7 = 0ull;       \
        _Pragma("unroll")                                                    \
        for (int q = 1; q < 12; q++) {                                       \
            ulonglong2 e = pv[q];                                            \
            if (q & 1) {                                                     \
                c1 = fma2(e.x, etp0[2*q],     c1);                           \
                c3 = fma2(e.y, etp0[2*q + 1], c3);                           \
                c5 = fma2(e.x, etp1[2*q],     c5);                           \
                c7 = fma2(e.y, etp1[2*q + 1], c7);                           \
            } else {                                                         \
                c0 = fma2(e.x, etp0[2*q],     c0);                           \
                c2 = fma2(e.y, etp0[2*q + 1], c2);                           \
                c4 = fma2(e.x, etp1[2*q],     c4);                           \
                c6 = fma2(e.y, etp1[2*q + 1], c6);                           \
            }                                                                \
        }                                                                    \
        unsigned long long sum0 = add2(add2(c0, c1), add2(c2, c3));          \
        unsigned long long sum1 = add2(add2(c4, c5), add2(c6, c7));          \
        float fpe = 0.0f;                                                    \
        if (RENORM) {                                                        \
            unsigned int pexp = ((unsigned)e0.x) >> 23;                      \
            int pe = (pexp - 1u < 254u) ? (int)pexp - 127 : 0;               \
            Cint += pe;                                                      \
            fpe = (float)(-pe);                                              \
        }                                                                    \
        float m0 = ex2f(fmaf((FC).x, LOG2E, fpe));                           \
        float m1 = ex2f(fmaf((FC).y, LOG2E, fpe));                           \
        float l0, h0, l1, h1;                                                \
        unpack2(sum0, l0, h0);                                               \
        unpack2(sum1, l1, h1);                                               \
        (POUT)[lane] = make_float2((l0 + h0) * m0, (l1 + h1) * m1);          \
    } while (0)

#define RUNLOOP(NSTEPS)                                                      \
    do {                                                                     \
        int t = 0;                                                           \
        _Pragma("unroll 1")                                                  \
        while (t + 1 < (NSTEPS)) {                                           \
            {                                                                \
                float2 fc = r1;                                              \
                r1 = r2; r2 = r3; r3 = r4;                                   \
                r4 = (t < pre) ? __ldg(pf) : make_float2(0.0f, 0.0f);        \
                pf += pstep;                                                 \
                STEP(s_p[0], s_p[1], fc, true);                              \
            }                                                                \
            __syncwarp();                                                    \
            {                                                                \
                float2 fc = r1;                                              \
                r1 = r2; r2 = r3; r3 = r4;                                   \
                r4 = (t + 1 < pre) ? __ldg(pf) : make_float2(0.0f, 0.0f);    \
                pf += pstep;                                                 \
                STEP(s_p[1], s_p[0], fc, false);                             \
            }                                                                \
            __syncwarp();                                                    \
            t += 2;                                                          \
        }                                                                    \
        if (t < (NSTEPS)) {                                                  \
            float2 fc = r1;                                                  \
            STEP(s_p[0], s_p[1], fc, true);                                  \
            __syncwarp();                                                    \
        }                                                                    \
    } while (0)

// second finisher: combine halves; last batch -> deterministic final sum
#define COMBINE(BATCH)                                                       \
    do {                                                                     \
        __threadfence();                                                     \
        float v = 0.0f;                                                      \
        if (act) {                                                           \
            float2 pfv = *(const float2*)&g_fwdv[(BATCH) * KK + sc];         \
            float2 bbv = *(const float2*)&g_bwdv[(BATCH) * KK + sc];         \
            v = pfv.x * bbv.x + pfv.y * bbv.y;                               \
        }                                                                    \
        _Pragma("unroll")                                                    \
        for (int o = 16; o; o >>= 1) v += __shfl_xor_sync(~0u, v, o);        \
        float logz = (float)(g_cf[BATCH] + g_cb[BATCH]) * LN2F + __logf(v);  \
        int l2 = 0;                                                          \
        if (lane == 0) {                                                     \
            g_partial[BATCH] = logz - g_gold[BATCH];                         \
            __threadfence();                                                 \
            int p2 = atomicAdd(&g_done, 1);                                  \
            l2 = (p2 == BB - 1);                                             \
        }                                                                    \
        l2 = __shfl_sync(~0u, l2, 0);                                        \
        if (l2) {                                                            \
            __threadfence();                                                 \
            float a = 0.0f;                                                  \
            _Pragma("unroll")                                                \
            for (int i = 0; i < BB / 32; i++)                                \
                a += g_partial[lane + i * 32];                               \
            _Pragma("unroll")                                                \
            for (int o = 16; o; o >>= 1) a += __shfl_xor_sync(~0u, a, o);    \
            if (lane == 0) out[0] = a;                                       \
        }                                                                    \
    } while (0)

__global__ void __launch_bounds__(32, 14) crf_kernel(
    const float* __restrict__ feats,
    const float* __restrict__ trans,
    const int*   __restrict__ tags,
    const int*   __restrict__ lengths,
    float*       __restrict__ out)
{
    __shared__ __align__(16) float2 s_p[2][32];    // pairs; 24..31 pads

    const int jb   = blockIdx.x;                   // job = rank jb>>1, dir jb&1
    const int lane = threadIdx.x;
    const bool act = (lane < 24);
    const int sc = act ? 2 * lane : 44;            // clamped state index
    const int s0 = sc, s1 = sc + 1;
    const bool is_fwd = ((jb & 1) == 0);

    const int b   = __ldg(&g_order[jb >> 1]);
    const int len = __ldg(lengths + b);
    const int m   = len >> 1;
    const int nst = is_fwd ? m : (len - m);

    // weight tables from gmem (L1/L2-cached): fwd = rows, bwd = columns
    unsigned long long etp0[24], etp1[24];
    #pragma unroll
    for (int i = 0; i < 24; i++) {
        if (is_fwd) {
            etp0[i] = pack2(__expf(__ldg(trans + s0 * KK + 2*i)),
                            __expf(__ldg(trans + s0 * KK + 2*i + 1)));
            etp1[i] = pack2(__expf(__ldg(trans + s1 * KK + 2*i)),
                            __expf(__ldg(trans + s1 * KK + 2*i + 1)));
        } else {
            etp0[i] = pack2(__expf(__ldg(trans + (2*i) * KK + s0)),
                            __expf(__ldg(trans + (2*i + 1) * KK + s0)));
            etp1[i] = pack2(__expf(__ldg(trans + (2*i) * KK + s1)),
                            __expf(__ldg(trans + (2*i + 1) * KK + s1)));
        }
    }
    const long long FS = (long long)BB * KK;
    const long long pstep = (FS / 2) * (is_fwd ? 1 : -1);
    const float* fb = feats + (long long)b * KK;

    int Cint = 0;
    float2 r1 = {0,0}, r2 = {0,0}, r3 = {0,0}, r4 = {0,0};
    const float2* pf;
    int pre;

    if (is_fwd) {
        s_p[0][lane] = (lane == 23) ? make_float2(1.0f, 0.0f)
                                    : make_float2(0.0f, 0.0f);  // START=46
        s_p[1][lane] = make_float2(0.0f, 0.0f);
        r1 = __ldg((const float2*)(fb + sc));       // t=0 (len >= 1)
        if (1 < nst) r2 = __ldg((const float2*)(fb + 1 * FS + sc));
        if (2 < nst) r3 = __ldg((const float2*)(fb + 2 * FS + sc));
        if (3 < nst) r4 = __ldg((const float2*)(fb + 3 * FS + sc));
        pf = (const float2*)(fb + sc) + (long long)PFD * (FS / 2);
        pre = nst - PFD;
    } else {
        // init: W_{len-1} = ef_{len-1} (.) exp(trans[STOP, :])
        float st0 = __expf(__ldg(trans + STOP_TAG * KK + s0));
        float st1 = __expf(__ldg(trans + STOP_TAG * KK + s1));
        float2 f0 = __ldg((const float2*)(fb + (long long)(len - 1) * FS + sc));
        s_p[0][lane] = make_float2(st0 * ex2f(f0.x * LOG2E),
                                   st1 * ex2f(f0.y * LOG2E));
        s_p[1][lane] = make_float2(0.0f, 0.0f);
        const float2* fp2 = (const float2*)(fb + sc);
        if (0 < nst - 1) r1 = __ldg(fp2 + (long long)(len - 2) * (FS / 2));
        if (1 < nst - 1) r2 = __ldg(fp2 + (long long)(len - 3) * (FS / 2));
        if (2 < nst - 1) r3 = __ldg(fp2 + (long long)(len - 4) * (FS / 2));
        if (3 < nst - 1) r4 = __ldg(fp2 + (long long)(len - 5) * (FS / 2));
        pf = fp2 + (long long)(len - 2 - PFD) * (FS / 2);
        pre = nst - 1 - PFD;
    }
    __syncwarp();

    RUNLOOP(nst);

    // publish this half's meeting vector
    if (act) {
        float* gv = is_fwd ? g_fwdv : g_bwdv;
        *(float2*)&gv[b * KK + sc] = s_p[nst & 1][lane];
    }

    if (is_fwd) {
        // gold score over the full sequence (32 lanes, gmem trans)
        const int* tg = tags + b * TT;
        float g = 0.0f;
        for (int q = lane; q < len; q += 32) {
            int nxt = __ldg(tg + q);
            int prv = (q == 0) ? START_TAG : __ldg(tg + q - 1);
            g += __ldg(trans + nxt * KK + prv) + __ldg(fb + (long long)q * FS + nxt);
        }
        #pragma unroll
        for (int o = 16; o; o >>= 1) g += __shfl_xor_sync(~0u, g, o);
        if (lane == 0) {
            g_gold[b] = g + __ldg(trans + STOP_TAG * KK + __ldg(tg + len - 1));
            g_cf[b] = Cint;
        }
    } else {
        if (lane == 0) g_cb[b] = Cint;
    }

    int prev = 0;
    if (lane == 0) {
        __threadfence();
        prev = atomicAdd(&g_flag[b], 1);
    }
    prev = __shfl_sync(~0u, prev, 0);
    if (prev == 1) COMBINE(b);
}

extern "C" void kernel_launch(void* const* d_in, const int* in_sizes, int n_in,
                              void* d_out, int out_size) {
    const float* feats   = (const float*)d_in[0];
    const float* trans   = (const float*)d_in[1];
    const int*   tags    = (const int*)d_in[2];
    const int*   lengths = (const int*)d_in[3];
    perm_kernel<<<2, 512>>>(lengths);
    crf_kernel<<<NBLK, 32>>>(feats, trans, tags, lengths, (float*)d_out);
}